// round 10
// baseline (speedup 1.0000x reference)
#include <cuda_runtime.h>
#include <cuda_bf16.h>
#include <cstdint>

#define HDIM 1024
#define NEXP 64
#define KTOP 8
#define BM   128
#define KC   64
#define NCHUNK 16
#define NTHREADS 256

#define B_STAGE 24576                    // 3 splits x 4 kt x 2 nh x 2 ntp x 32 x 16B
#define SMEM_TOTAL (4 * B_STAGE)         // 98304 B (logits overlay after the loop)

__device__ unsigned short g_wp[3 * 64 * 2 * 2 * 32 * 8];  // W splits, frag-permuted
__device__ float    g_esum[NEXP];
__device__ int      g_ecnt[NEXP];
__device__ unsigned g_done = 0;

__device__ __forceinline__ unsigned smem_u32(const void* p) {
    return (unsigned)__cvta_generic_to_shared(p);
}
__device__ __forceinline__ void cp16(unsigned dst, const void* src) {
    asm volatile("cp.async.cg.shared.global [%0], [%1], 16;\n" :: "r"(dst), "l"(src));
}
__device__ __forceinline__ void cp_commit() { asm volatile("cp.async.commit_group;\n"); }
__device__ __forceinline__ void cp_wait2()  { asm volatile("cp.async.wait_group 2;\n" ::: "memory"); }

__device__ __forceinline__ uint32_t cvt_bf16x2(float hi, float lo) {  // hi -> upper half
    uint32_t d; asm("cvt.rn.bf16x2.f32 %0, %1, %2;" : "=r"(d) : "f"(hi), "f"(lo)); return d;
}
__device__ __forceinline__ float ubflo(uint32_t u) { return __uint_as_float(u << 16); }
__device__ __forceinline__ float ubfhi(uint32_t u) { return __uint_as_float(u & 0xFFFF0000u); }

__device__ __forceinline__ void lds128(uint32_t* r, unsigned a) {
    asm volatile("ld.shared.v4.u32 {%0,%1,%2,%3}, [%4];"
                 : "=r"(r[0]), "=r"(r[1]), "=r"(r[2]), "=r"(r[3]) : "r"(a));
}
// D(16x8,f32) += A(16x16,bf16 row) x B(16x8,bf16 col)
__device__ __forceinline__ void mma16816(float* d, const uint32_t* a, const uint32_t* b) {
    asm volatile("mma.sync.aligned.m16n8k16.row.col.f32.bf16.bf16.f32 "
                 "{%0,%1,%2,%3}, {%4,%5,%6,%7}, {%8,%9}, {%0,%1,%2,%3};"
                 : "+f"(d[0]), "+f"(d[1]), "+f"(d[2]), "+f"(d[3])
                 : "r"(a[0]), "r"(a[1]), "r"(a[2]), "r"(a[3]), "r"(b[0]), "r"(b[1]));
}

// Split W (rounded 3-way) and store in B-fragment-permuted layout (proven R8/R9).
__global__ void wsplit_k(const float* __restrict__ W) {
    int i = blockIdx.x * 256 + threadIdx.x;   // i = n*1024 + k
    int n = i >> 10, k = i & 1023;
    float x = W[i];
    __nv_bfloat16 bh = __float2bfloat16_rn(x);
    float r1 = x - __bfloat162float(bh);
    __nv_bfloat16 bm = __float2bfloat16_rn(r1);
    float r2 = r1 - __bfloat162float(bm);
    __nv_bfloat16 bl = __float2bfloat16_rn(r2);
    unsigned short hv[3];
    hv[0] = *reinterpret_cast<unsigned short*>(&bh);
    hv[1] = *reinterpret_cast<unsigned short*>(&bm);
    hv[2] = *reinterpret_cast<unsigned short*>(&bl);

    int kt = k >> 4, kl = k & 15;
    int lane = ((n & 7) << 2) | ((kl >> 1) & 3);
    int reg  = (kl >> 3) & 1;
    int nh   = n >> 5, ntp = (n >> 4) & 1;
    int w4   = ((n >> 3) & 1) * 2 + reg;
    #pragma unroll
    for (int s = 0; s < 3; ++s) {
        size_t off = ((((size_t)s * 64 + kt) * 2 + nh) * 2 + ntp) * 32 + lane;  // 16B units
        g_wp[off * 8 + w4 * 2 + (kl & 1)] = hv[s];
    }
}

extern __shared__ char dynsm[];

__global__ __launch_bounds__(NTHREADS, 1)
void gate_k(const float* __restrict__ X,
            float* __restrict__ outIdx, float* __restrict__ outW,
            float* __restrict__ outAux, int N) {
    const int tid  = threadIdx.x;
    const int lane = tid & 31;
    const int w    = tid >> 5;          // warp = m-tile (16 tokens), all 64 experts
    const unsigned sbu = smem_u32(dynsm);

    const float* Xw = X + (size_t)blockIdx.x * BM * HDIM
                        + (size_t)(w * 16 + (lane >> 2)) * HDIM + (lane & 3) * 2;

    auto loadB = [&](int c) {
        #pragma unroll
        for (int t = 0; t < 6; ++t) {
            int j = tid + t * 256;                  // 1536 16B units per stage
            int s = j >> 9, rem = j & 511;
            cp16(sbu + (c & 3) * B_STAGE + (unsigned)j * 16,
                 (const char*)g_wp + (((size_t)s * 64 + c * 4) * 128 + rem) * 16);
        }
        cp_commit();
    };
    auto loadX = [&](int c, float2* xv) {
        const float* p = Xw + c * KC;
        #pragma unroll
        for (int kt = 0; kt < 4; ++kt) {
            xv[kt * 4 + 0] = *(const float2*)(p + kt * 16);
            xv[kt * 4 + 1] = *(const float2*)(p + kt * 16 + 8);
            xv[kt * 4 + 2] = *(const float2*)(p + kt * 16 + 8 * HDIM);
            xv[kt * 4 + 3] = *(const float2*)(p + kt * 16 + 8 * HDIM + 8);
        }
    };

    float2 xc[16], xn[16];
    loadX(0, xc);
    loadB(0);
    loadB(1);

    float accH[8][4] = {}, accL[8][4] = {}, kS[8][4] = {};

    for (int c = 0; c < NCHUNK; ++c) {
        // issue next-next B stage FIRST so the DMA overlaps this chunk's compute.
        // Safe: stage (c+2)&3 was last read in chunk c-2; the barrier below (entered
        // only after every warp finished chunk c-1) guarantees those reads are done.
        __syncthreads();
        if (c + 2 < NCHUNK) loadB(c + 2); else cp_commit();
        cp_wait2();          // stage c resident (c+1, c+2 may be in flight)

        if (c + 1 < NCHUNK) loadX(c + 1, xn);

        const unsigned bB = sbu + (c & 3) * B_STAGE;
        #pragma unroll
        for (int kt = 0; kt < 4; ++kt) {
            // convert this kt's A fragment -> 3 bf16x2 fragments, in registers
            uint32_t ah[4], am[4], aq[4];
            {
                const int src[4] = { 4 * kt + 0, 4 * kt + 2, 4 * kt + 1, 4 * kt + 3 };
                #pragma unroll
                for (int f = 0; f < 4; ++f) {
                    float2 v = xc[src[f]];
                    uint32_t h = cvt_bf16x2(v.y, v.x);
                    float r1x = v.x - ubflo(h), r1y = v.y - ubfhi(h);
                    uint32_t m = cvt_bf16x2(r1y, r1x);
                    float r2x = r1x - ubflo(m), r2y = r1y - ubfhi(m);
                    ah[f] = h; am[f] = m;
                    aq[f] = cvt_bf16x2(r2y, r2x);
                }
            }
            // burst-load ALL 12 B fragments of this kt (overlapped LDS latencies)
            uint32_t bf[48];
            #pragma unroll
            for (int s = 0; s < 3; ++s)
                #pragma unroll
                for (int qd = 0; qd < 4; ++qd)
                    lds128(bf + (s * 4 + qd) * 4,
                           bB + (unsigned)(((((s * 4 + kt) * 2 + (qd >> 1)) * 2 + (qd & 1)) * 32 + lane) * 16));
            // pass-outer / qd-inner: same-accumulator MMAs spaced 8 apart
            #pragma unroll
            for (int qd = 0; qd < 4; ++qd) {  // hh -> accH
                mma16816(accH[qd * 2],     ah, bf + qd * 4);
                mma16816(accH[qd * 2 + 1], ah, bf + qd * 4 + 2);
            }
            #pragma unroll
            for (int qd = 0; qd < 4; ++qd) {  // mh -> accL
                mma16816(accL[qd * 2],     am, bf + qd * 4);
                mma16816(accL[qd * 2 + 1], am, bf + qd * 4 + 2);
            }
            #pragma unroll
            for (int qd = 0; qd < 4; ++qd) {  // lh -> accL
                mma16816(accL[qd * 2],     aq, bf + qd * 4);
                mma16816(accL[qd * 2 + 1], aq, bf + qd * 4 + 2);
            }
            #pragma unroll
            for (int qd = 0; qd < 4; ++qd) {  // hm -> accL
                mma16816(accL[qd * 2],     ah, bf + 16 + qd * 4);
                mma16816(accL[qd * 2 + 1], ah, bf + 16 + qd * 4 + 2);
            }
            #pragma unroll
            for (int qd = 0; qd < 4; ++qd) {  // mm -> accL
                mma16816(accL[qd * 2],     am, bf + 16 + qd * 4);
                mma16816(accL[qd * 2 + 1], am, bf + 16 + qd * 4 + 2);
            }
            #pragma unroll
            for (int qd = 0; qd < 4; ++qd) {  // hl -> accL
                mma16816(accL[qd * 2],     ah, bf + 32 + qd * 4);
                mma16816(accL[qd * 2 + 1], ah, bf + 32 + qd * 4 + 2);
            }
        }

        #pragma unroll
        for (int i = 0; i < 16; ++i) xc[i] = xn[i];

        if (c & 1) {  // fold accH partial (8 accumulate steps) into master sums
            #pragma unroll
            for (int nt = 0; nt < 8; ++nt)
                #pragma unroll
                for (int q = 0; q < 4; ++q) { kS[nt][q] += accH[nt][q]; accH[nt][q] = 0.0f; }
        }
    }
    __syncthreads();   // everyone done with B smem -> overlay logits

    // ---- write logits [128][66] ----
    float* lg = (float*)dynsm;
    {
        int r0 = w * 16 + (lane >> 2);
        int n0 = (lane & 3) * 2;
        #pragma unroll
        for (int nt = 0; nt < 8; ++nt) {
            float f0 = kS[nt][0] + accL[nt][0];
            float f1 = kS[nt][1] + accL[nt][1];
            float f2 = kS[nt][2] + accL[nt][2];
            float f3 = kS[nt][3] + accL[nt][3];
            *(float2*)(lg + r0 * 66 + nt * 8 + n0)       = make_float2(f0, f1);
            *(float2*)(lg + (r0 + 8) * 66 + nt * 8 + n0) = make_float2(f2, f3);
        }
    }
    __syncthreads();

    // ---- softmax + top-8: warp w -> tokens [16w, 16w+16) ----
    float ls0 = 0.0f, ls1 = 0.0f;
    int   c0  = 0,    c1  = 0;
    for (int t = w * 16; t < w * 16 + 16; ++t) {
        float l0 = lg[t * 66 + lane];
        float l1 = lg[t * 66 + 32 + lane];
        float m = fmaxf(l0, l1);
        #pragma unroll
        for (int off = 16; off; off >>= 1)
            m = fmaxf(m, __shfl_xor_sync(0xffffffffu, m, off));
        float s0 = expf(l0 - m), s1 = expf(l1 - m);
        float z = s0 + s1;
        #pragma unroll
        for (int off = 16; off; off >>= 1)
            z += __shfl_xor_sync(0xffffffffu, z, off);
        s0 /= z; s1 /= z;
        ls0 += s0; ls1 += s1;

        float r0 = s0, r1 = s1;
        float sumTop = 0.0f, myS = 0.0f;
        int myIdx = 0;
        #pragma unroll
        for (int r = 0; r < KTOP; ++r) {
            float v; int id;
            if (r0 >= r1) { v = r0; id = lane; }       // tie -> lower index
            else          { v = r1; id = lane + 32; }
            #pragma unroll
            for (int off = 16; off; off >>= 1) {
                float v2 = __shfl_xor_sync(0xffffffffu, v, off);
                int   i2 = __shfl_xor_sync(0xffffffffu, id, off);
                if (v2 > v || (v2 == v && i2 < id)) { v = v2; id = i2; }
            }
            sumTop += v;
            if (lane == r) { myS = v; myIdx = id; }
            if (id == lane)           { r0 = -1.0f; c0++; }
            else if (id == lane + 32) { r1 = -1.0f; c1++; }
        }
        if (lane < KTOP) {
            size_t gt = (size_t)(blockIdx.x * BM + t) * KTOP + lane;
            outIdx[gt] = (float)myIdx;
            outW[gt]   = myS / (sumTop + 1e-20f);
        }
    }

    // ---- CTA reduction + 64 global atomics ----
    float* redS = (float*)dynsm + 8448;          // beyond lg (128*66)
    float* redC = redS + 512;
    redS[w * 64 + lane]      = ls0;
    redS[w * 64 + lane + 32] = ls1;
    redC[w * 64 + lane]      = (float)c0;
    redC[w * 64 + lane + 32] = (float)c1;
    __syncthreads();
    if (tid < NEXP) {
        float es = 0.0f, ec = 0.0f;
        #pragma unroll
        for (int ww = 0; ww < 8; ++ww) {
            es += redS[ww * 64 + tid];
            ec += redC[ww * 64 + tid];
        }
        atomicAdd(&g_esum[tid], es);
        if (ec != 0.0f) atomicAdd(&g_ecnt[tid], (int)ec);
    }

    // ---- last-CTA aux finalize ----
    __shared__ unsigned s_isLast;
    __threadfence();
    __syncthreads();
    if (tid == 0)
        s_isLast = (atomicAdd(&g_done, 1u) == gridDim.x - 1) ? 1u : 0u;
    __syncthreads();
    if (s_isLast && tid < 32) {
        float p = g_esum[tid] * (float)g_ecnt[tid]
                + g_esum[tid + 32] * (float)g_ecnt[tid + 32];
        g_esum[tid] = 0.0f;  g_esum[tid + 32] = 0.0f;
        g_ecnt[tid] = 0;     g_ecnt[tid + 32] = 0;
        #pragma unroll
        for (int off = 16; off; off >>= 1)
            p += __shfl_xor_sync(0xffffffffu, p, off);
        if (tid == 0) {
            g_done = 0;
            float denom = (float)N * (float)(N * KTOP);
            *outAux = 0.01f * 64.0f * p / denom;   // ALPHA * E * sum / (N * N*K)
        }
    }
}

extern "C" void kernel_launch(void* const* d_in, const int* in_sizes, int n_in,
                              void* d_out, int out_size) {
    const float* X = (const float*)d_in[0];   // [4,8192,1024] f32
    const float* W = (const float*)d_in[1];   // [64,1024] f32
    float* out = (float*)d_out;               // [idx N*8 | weight N*8 | aux 1]
    int N = in_sizes[0] / HDIM;               // 32768

    cudaFuncSetAttribute(gate_k, cudaFuncAttributeMaxDynamicSharedMemorySize, SMEM_TOTAL);
    wsplit_k<<<NEXP * HDIM / 256, 256>>>(W);
    gate_k<<<N / BM, NTHREADS, SMEM_TOTAL>>>(X, out, out + (size_t)N * KTOP,
                                             out + (size_t)2 * N * KTOP, N);
}